// round 1
// baseline (speedup 1.0000x reference)
#include <cuda_runtime.h>
#include <math.h>

// Problem dims
#define BSZ  4096
#define TT   32
#define ROLL 130
#define RHY  3
#define COND 12
#define NZ1  128
#define HH   1024
#define IN1  273
#define IN1P 288          // K padded to multiple of 16
#define G3   (3 * HH)     // 3072

// ---------------- scratch (device globals; no allocation allowed) ----------
__device__ float g_x[BSZ * IN1P];        // step input, padded
__device__ float g_wih1p[G3 * IN1P];     // zero-padded w_ih1
__device__ float g_gi[BSZ * G3];
__device__ float g_gh[BSZ * G3];
__device__ float g_h1[BSZ * HH];
__device__ float g_h2[BSZ * HH];
__device__ float g_logits[BSZ * ROLL];
__device__ int   g_oidx[BSZ];

// ---------------- f32x2 helpers (sm_103a packed fp32 pipe) -----------------
__device__ __forceinline__ unsigned long long fma2(unsigned long long a,
                                                   unsigned long long b,
                                                   unsigned long long c) {
    unsigned long long d;
    asm("fma.rn.f32x2 %0, %1, %2, %3;" : "=l"(d) : "l"(a), "l"(b), "l"(c));
    return d;
}
__device__ __forceinline__ unsigned long long pack2(float x) {
    unsigned long long d;
    asm("mov.b64 %0, {%1, %2};" : "=l"(d) : "f"(x), "f"(x));
    return d;
}

// ---------------- GEMM: C[M,N] = A[M,K] @ W[N,K]^T + bias ------------------
// 128x128 tile, BK=16, 256 threads, 8x8 per thread (as 8x4 f32x2 pairs).
// Requires: M % 128 == 0, K % 16 == 0, K % 4 == 0. N guarded when NGUARD.
template <bool NGUARD, bool TANH>
__global__ void __launch_bounds__(256, 2)
gemm_kernel(const float* __restrict__ A, const float* __restrict__ W,
            const float* __restrict__ bias, float* __restrict__ C,
            int N, int K) {
    __shared__ float As[16][128];
    __shared__ float Ws[16][128];

    const int tid  = threadIdx.x;
    const int tcol = (tid & 15) << 3;   // 0..120 step 8
    const int trow = (tid >> 4) << 3;   // 0..120 step 8
    const int bm   = blockIdx.y * 128;
    const int bn   = blockIdx.x * 128;

    const int lrow = tid >> 2;          // 0..63
    const int lc4  = (tid & 3) << 2;    // 0,4,8,12

    unsigned long long acc[8][4];
#pragma unroll
    for (int i = 0; i < 8; i++)
#pragma unroll
        for (int j = 0; j < 4; j++) acc[i][j] = 0ULL;

    for (int k0 = 0; k0 < K; k0 += 16) {
#pragma unroll
        for (int l = 0; l < 2; l++) {
            int row = lrow + (l << 6);
            float4 av = *reinterpret_cast<const float4*>(
                &A[(size_t)(bm + row) * K + k0 + lc4]);
            As[lc4 + 0][row] = av.x;
            As[lc4 + 1][row] = av.y;
            As[lc4 + 2][row] = av.z;
            As[lc4 + 3][row] = av.w;
            float4 wv = make_float4(0.f, 0.f, 0.f, 0.f);
            if (!NGUARD || (bn + row) < N)
                wv = *reinterpret_cast<const float4*>(
                    &W[(size_t)(bn + row) * K + k0 + lc4]);
            Ws[lc4 + 0][row] = wv.x;
            Ws[lc4 + 1][row] = wv.y;
            Ws[lc4 + 2][row] = wv.z;
            Ws[lc4 + 3][row] = wv.w;
        }
        __syncthreads();
#pragma unroll
        for (int k = 0; k < 16; k++) {
            ulonglong2 b01 = *reinterpret_cast<const ulonglong2*>(&Ws[k][tcol]);
            ulonglong2 b23 = *reinterpret_cast<const ulonglong2*>(&Ws[k][tcol + 4]);
            float4 a0 = *reinterpret_cast<const float4*>(&As[k][trow]);
            float4 a1 = *reinterpret_cast<const float4*>(&As[k][trow + 4]);
            float av8[8] = {a0.x, a0.y, a0.z, a0.w, a1.x, a1.y, a1.z, a1.w};
#pragma unroll
            for (int i = 0; i < 8; i++) {
                unsigned long long ap = pack2(av8[i]);
                acc[i][0] = fma2(ap, b01.x, acc[i][0]);
                acc[i][1] = fma2(ap, b01.y, acc[i][1]);
                acc[i][2] = fma2(ap, b23.x, acc[i][2]);
                acc[i][3] = fma2(ap, b23.y, acc[i][3]);
            }
        }
        __syncthreads();
    }

#pragma unroll
    for (int i = 0; i < 8; i++) {
        int row = bm + trow + i;
#pragma unroll
        for (int j = 0; j < 4; j++) {
            int col = bn + tcol + 2 * j;
            if (NGUARD && col >= N) continue;
            float lo = __uint_as_float((unsigned)(acc[i][j] & 0xffffffffULL));
            float hi = __uint_as_float((unsigned)(acc[i][j] >> 32));
            float v0 = lo + bias[col];
            if (TANH) v0 = tanhf(v0);
            if (!NGUARD || (col + 1) < N) {
                float v1 = hi + bias[col + 1];
                if (TANH) v1 = tanhf(v1);
                *reinterpret_cast<float2*>(&C[(size_t)row * N + col]) =
                    make_float2(v0, v1);
            } else {
                C[(size_t)row * N + col] = v0;
            }
        }
    }
}

// ---------------- small kernels --------------------------------------------
__global__ void pad_wih1_kernel(const float* __restrict__ w) {
    int idx = blockIdx.x * blockDim.x + threadIdx.x;
    if (idx >= G3 * IN1P) return;
    int n = idx / IN1P, k = idx - n * IN1P;
    g_wih1p[idx] = (k < IN1) ? w[(size_t)n * IN1 + k] : 0.0f;
}

__global__ void init_oidx_kernel() {
    int b = blockIdx.x * blockDim.x + threadIdx.x;
    if (b < BSZ) g_oidx[b] = ROLL - 1;
}

__global__ void build_inp_kernel(const float* __restrict__ rhy,
                                 const float* __restrict__ z1,
                                 const float* __restrict__ cond, int t) {
    int idx = blockIdx.x * blockDim.x + threadIdx.x;
    if (idx >= BSZ * IN1P) return;
    int b = idx / IN1P, c = idx - b * IN1P;
    float v;
    if (c < ROLL) {
        v = (c == g_oidx[b]) ? 1.0f : 0.0f;
    } else if (c < ROLL + RHY) {
        v = rhy[(size_t)b * TT * RHY + (size_t)t * RHY + (c - ROLL)];
    } else if (c < ROLL + RHY + NZ1) {
        v = z1[(size_t)b * NZ1 + (c - ROLL - RHY)];
    } else if (c < IN1) {
        v = cond[(size_t)b * TT * COND + (size_t)t * COND + (c - ROLL - RHY - NZ1)];
    } else {
        v = 0.0f;
    }
    g_x[idx] = v;
}

__global__ void gru_update_kernel(const float* __restrict__ gi,
                                  const float* __restrict__ gh,
                                  const float* hprev, float* hout) {
    int idx = blockIdx.x * blockDim.x + threadIdx.x;
    if (idx >= BSZ * HH) return;
    int b = idx >> 10, j = idx & (HH - 1);
    size_t o = (size_t)b * G3 + j;
    float ir = gi[o], iz = gi[o + HH], in_ = gi[o + 2 * HH];
    float hr = gh[o], hz = gh[o + HH], hn = gh[o + 2 * HH];
    float r = 1.0f / (1.0f + expf(-(ir + hr)));
    float z = 1.0f / (1.0f + expf(-(iz + hz)));
    float n = tanhf(in_ + r * hn);
    hout[idx] = (1.0f - z) * n + z * hprev[idx];
}

// one warp per batch row: log_softmax -> recon[b,t,:], argmax -> g_oidx[b]
__global__ void softmax_argmax_kernel(float* __restrict__ recon, int t) {
    int gw = (blockIdx.x * blockDim.x + threadIdx.x) >> 5;
    int lane = threadIdx.x & 31;
    if (gw >= BSZ) return;
    const float* lg = &g_logits[(size_t)gw * ROLL];
    float vals[5];
    float mx = -1e30f;
#pragma unroll
    for (int j = 0; j < 5; j++) {
        int n = lane + 32 * j;
        vals[j] = (n < ROLL) ? lg[n] : -1e30f;
        mx = fmaxf(mx, vals[j]);
    }
#pragma unroll
    for (int s = 16; s; s >>= 1) mx = fmaxf(mx, __shfl_xor_sync(0xffffffffu, mx, s));
    float se = 0.0f;
#pragma unroll
    for (int j = 0; j < 5; j++) {
        int n = lane + 32 * j;
        if (n < ROLL) se += expf(vals[j] - mx);
    }
#pragma unroll
    for (int s = 16; s; s >>= 1) se += __shfl_xor_sync(0xffffffffu, se, s);
    float lse = logf(se);
    float* out = &recon[(size_t)gw * (TT * ROLL) + (size_t)t * ROLL];
#pragma unroll
    for (int j = 0; j < 5; j++) {
        int n = lane + 32 * j;
        if (n < ROLL) out[n] = vals[j] - mx - lse;
    }
    // argmax (first occurrence of max, matching jnp.argmax)
    float bv = -1e30f;
    int bi = ROLL;
#pragma unroll
    for (int j = 0; j < 5; j++) {
        int n = lane + 32 * j;
        if (n < ROLL && vals[j] > bv) { bv = vals[j]; bi = n; }
    }
#pragma unroll
    for (int s = 16; s; s >>= 1) {
        float ov = __shfl_xor_sync(0xffffffffu, bv, s);
        int oi = __shfl_xor_sync(0xffffffffu, bi, s);
        if (ov > bv || (ov == bv && oi < bi)) { bv = ov; bi = oi; }
    }
    if (lane == 0) g_oidx[gw] = bi;
}

// ---------------- launch ----------------------------------------------------
extern "C" void kernel_launch(void* const* d_in, const int* in_sizes, int n_in,
                              void* d_out, int out_size) {
    const float* z1    = (const float*)d_in[0];
    const float* d1m   = (const float*)d_in[1];
    const float* d1s   = (const float*)d_in[2];
    const float* d2m   = (const float*)d_in[3];
    const float* d2s   = (const float*)d_in[4];
    const float* rhy   = (const float*)d_in[5];
    // d_in[6] = sample (unused in eval path)
    const float* cond  = (const float*)d_in[7];
    // d_in[8] = iteration (unused in eval path)
    const float* w_ih1 = (const float*)d_in[9];
    const float* w_hh1 = (const float*)d_in[10];
    const float* b_ih1 = (const float*)d_in[11];
    const float* b_hh1 = (const float*)d_in[12];
    const float* w_ih2 = (const float*)d_in[13];
    const float* w_hh2 = (const float*)d_in[14];
    const float* b_ih2 = (const float*)d_in[15];
    const float* b_hh2 = (const float*)d_in[16];
    const float* w_init = (const float*)d_in[17];
    const float* b_init = (const float*)d_in[18];
    const float* w_out  = (const float*)d_in[19];
    const float* b_out  = (const float*)d_in[20];

    float* out = (float*)d_out;
    float* recon = out;

    float *p_x, *p_w1p, *p_gi, *p_gh, *p_h1, *p_h2, *p_lg;
    cudaGetSymbolAddress((void**)&p_x, g_x);
    cudaGetSymbolAddress((void**)&p_w1p, g_wih1p);
    cudaGetSymbolAddress((void**)&p_gi, g_gi);
    cudaGetSymbolAddress((void**)&p_gh, g_gh);
    cudaGetSymbolAddress((void**)&p_h1, g_h1);
    cudaGetSymbolAddress((void**)&p_h2, g_h2);
    cudaGetSymbolAddress((void**)&p_lg, g_logits);

    // prep (re-run every call: deterministic, no caching)
    pad_wih1_kernel<<<(G3 * IN1P + 255) / 256, 256>>>(w_ih1);
    init_oidx_kernel<<<(BSZ + 255) / 256, 256>>>();

    // h1_0 = tanh(z1 @ w_init^T + b_init)
    gemm_kernel<false, true><<<dim3(HH / 128, BSZ / 128), 256>>>(
        z1, w_init, b_init, p_h1, HH, NZ1);

    const dim3 gemm_grid(G3 / 128, BSZ / 128);
    for (int t = 0; t < TT; t++) {
        build_inp_kernel<<<(BSZ * IN1P + 255) / 256, 256>>>(rhy, z1, cond, t);
        // GRU cell 1
        gemm_kernel<false, false><<<gemm_grid, 256>>>(p_x, p_w1p, b_ih1, p_gi, G3, IN1P);
        gemm_kernel<false, false><<<gemm_grid, 256>>>(p_h1, w_hh1, b_hh1, p_gh, G3, HH);
        gru_update_kernel<<<(BSZ * HH + 255) / 256, 256>>>(p_gi, p_gh, p_h1, p_h1);
        // GRU cell 2 (h2 := h1 at t==0)
        const float* h2prev = (t == 0) ? p_h1 : p_h2;
        gemm_kernel<false, false><<<gemm_grid, 256>>>(p_h1, w_ih2, b_ih2, p_gi, G3, HH);
        gemm_kernel<false, false><<<gemm_grid, 256>>>(h2prev, w_hh2, b_hh2, p_gh, G3, HH);
        gru_update_kernel<<<(BSZ * HH + 255) / 256, 256>>>(p_gi, p_gh, h2prev, p_h2);
        // logits -> log_softmax -> recon + argmax feedback
        gemm_kernel<true, false><<<dim3(2, BSZ / 128), 256>>>(
            p_h2, w_out, b_out, p_lg, ROLL, HH);
        softmax_argmax_kernel<<<BSZ / 4, 128>>>(recon, t);
    }

    // pass-through outputs
    const size_t RECON_N = (size_t)BSZ * TT * ROLL;   // 17,039,360
    const size_t RHY_N   = (size_t)BSZ * TT * RHY;    //    393,216
    const size_t DIS_N   = (size_t)BSZ * NZ1;         //    524,288
    cudaMemcpyAsync(out + RECON_N, rhy, RHY_N * sizeof(float), cudaMemcpyDeviceToDevice);
    cudaMemcpyAsync(out + RECON_N + RHY_N, d1m, DIS_N * sizeof(float), cudaMemcpyDeviceToDevice);
    cudaMemcpyAsync(out + RECON_N + RHY_N + DIS_N, d1s, DIS_N * sizeof(float), cudaMemcpyDeviceToDevice);
    cudaMemcpyAsync(out + RECON_N + RHY_N + 2 * DIS_N, d2m, DIS_N * sizeof(float), cudaMemcpyDeviceToDevice);
    cudaMemcpyAsync(out + RECON_N + RHY_N + 3 * DIS_N, d2s, DIS_N * sizeof(float), cudaMemcpyDeviceToDevice);
}

// round 14
// speedup vs baseline: 2.1558x; 2.1558x over previous
#include <cuda_runtime.h>
#include <cuda_bf16.h>
#include <cstdint>
#include <math.h>

// ---------------- problem dims ----------------
#define BSZ  4096
#define TT   32
#define ROLL 130
#define RHY  3
#define COND 12
#define NZ1  128
#define HH   1024
#define IN1  273
#define IN1P 320          // padded to multiple of 32 (BK)
#define G3   (3 * HH)     // 3072

// ---------------- scratch (device globals; no allocation allowed) ----------
__device__ float g_gi[BSZ * G3];
__device__ float g_gh[BSZ * G3];
__device__ float g_h1[BSZ * HH];
__device__ float g_h2[BSZ * HH];
__device__ float g_logits[BSZ * ROLL];
__device__ int   g_oidx[BSZ];

__device__ __nv_bfloat16 g_xh[BSZ * IN1P], g_xl[BSZ * IN1P];
__device__ __nv_bfloat16 g_h1h[BSZ * HH],  g_h1l[BSZ * HH];
__device__ __nv_bfloat16 g_h2h[BSZ * HH],  g_h2l[BSZ * HH];
__device__ __nv_bfloat16 g_w1h[G3 * IN1P], g_w1l[G3 * IN1P];
__device__ __nv_bfloat16 g_whh1h[G3 * HH], g_whh1l[G3 * HH];
__device__ __nv_bfloat16 g_wih2h[G3 * HH], g_wih2l[G3 * HH];
__device__ __nv_bfloat16 g_whh2h[G3 * HH], g_whh2l[G3 * HH];

// ================= portable-PTX helpers (sm_80+ subset; NO tcgen05) ========
__device__ __forceinline__ void cp16(uint32_t s, const void* g) {
    asm volatile("cp.async.cg.shared.global [%0], [%1], 16;" :: "r"(s), "l"(g));
}
__device__ __forceinline__ void cp_commit() {
    asm volatile("cp.async.commit_group;" ::: "memory");
}
template <int N> __device__ __forceinline__ void cp_wait() {
    asm volatile("cp.async.wait_group %0;" :: "n"(N) : "memory");
}
__device__ __forceinline__ uint32_t smem_to_u32(const void* p) {
    uint32_t a;
    asm("{ .reg .u64 t; cvta.to.shared.u64 t, %1; cvt.u32.u64 %0, t; }"
        : "=r"(a) : "l"(p));
    return a;
}
__device__ __forceinline__ void mma16816(float* d, const uint32_t* a,
                                         const uint32_t* b) {
    asm volatile(
        "mma.sync.aligned.m16n8k16.row.col.f32.bf16.bf16.f32 "
        "{%0,%1,%2,%3}, {%4,%5,%6,%7}, {%8,%9}, {%0,%1,%2,%3};"
        : "+f"(d[0]), "+f"(d[1]), "+f"(d[2]), "+f"(d[3])
        : "r"(a[0]), "r"(a[1]), "r"(a[2]), "r"(a[3]), "r"(b[0]), "r"(b[1]));
}
__device__ __forceinline__ uint32_t lds32(uint32_t addr) {
    uint32_t v;
    asm volatile("ld.shared.b32 %0, [%1];" : "=r"(v) : "r"(addr));
    return v;
}

// ================= tensor-core (HMMA) split-bf16 GEMM ======================
// C[M, Ntot] = (Ah+Al)[M,K] @ (Wh+Wl)[Ntot,K]^T + bias   (lo*lo dropped)
// BM=128, BN=128, BK=32, 8 warps (warp tile 64x32), cp.async double buffer.
// SMEM tiles row-padded: 32 bf16 cols stored with stride 40 elems (80 B).
#define ROWB 80                  // padded row stride in bytes
#define TILEB (128 * ROWB)       // 10240 B per tile
#define STAGEB (4 * TILEB)       // AH | AL | WH | WL = 40960 B
#define MMA_SMEM (2 * STAGEB)    // 81920 B

__global__ void __launch_bounds__(256)
gemm_mma(const __nv_bfloat16* __restrict__ Ah, const __nv_bfloat16* __restrict__ Al,
         const __nv_bfloat16* __restrict__ Wh, const __nv_bfloat16* __restrict__ Wl,
         const float* __restrict__ bias, float* __restrict__ C, int Ntot, int K) {
    extern __shared__ char smem[];
    const uint32_t sb = smem_to_u32(smem);
    const int tid  = threadIdx.x;
    const int wid  = tid >> 5, lane = tid & 31;
    const int wm   = wid >> 2;          // 0..1 -> 64 rows each
    const int wn   = wid & 3;           // 0..3 -> 32 cols each
    const int gid  = lane >> 2;         // group id 0..7
    const int tig  = lane & 3;          // thread in group
    const int bm   = blockIdx.y * 128;
    const int bn   = blockIdx.x * 128;
    const int KC   = K >> 5;            // chunks of 32

    const __nv_bfloat16* srcs[4] = {
        Ah + (size_t)bm * K, Al + (size_t)bm * K,
        Wh + (size_t)bn * K, Wl + (size_t)bn * K };

    // each stage: 4 tiles x 512 cp16 slots (128 rows x 4 16B-chunks)
    auto load_stage = [&](int kc, int stg) {
        const uint32_t base = sb + stg * STAGEB;
        const int kb = kc << 5;
#pragma unroll
        for (int tt = 0; tt < 4; tt++) {
            const __nv_bfloat16* src = srcs[tt];
#pragma unroll
            for (int j = 0; j < 2; j++) {
                int idx = tid + (j << 8);        // 0..511
                int row = idx >> 2, ch = idx & 3;
                cp16(base + tt * TILEB + row * ROWB + ch * 16,
                     src + (size_t)row * K + kb + (ch << 3));
            }
        }
        cp_commit();
    };

    float acc[4][4][4];
#pragma unroll
    for (int mt = 0; mt < 4; mt++)
#pragma unroll
        for (int nt = 0; nt < 4; nt++)
#pragma unroll
            for (int r = 0; r < 4; r++) acc[mt][nt][r] = 0.0f;

    load_stage(0, 0);
    for (int kc = 0; kc < KC; kc++) {
        if (kc + 1 < KC) { load_stage(kc + 1, (kc + 1) & 1); cp_wait<1>(); }
        else             { cp_wait<0>(); }
        __syncthreads();

        const uint32_t s0 = sb + (kc & 1) * STAGEB;
#pragma unroll
        for (int kt = 0; kt < 2; kt++) {
            const int c0 = (kt << 4) + (tig << 1);   // k col within 32
            uint32_t ah[4][4], al[4][4];
#pragma unroll
            for (int mt = 0; mt < 4; mt++) {
                int r0 = (wm << 6) + (mt << 4) + gid;
                uint32_t o00 = s0 + r0 * ROWB + c0 * 2;
                uint32_t o10 = o00 + 8 * ROWB;
                ah[mt][0] = lds32(o00);
                ah[mt][1] = lds32(o10);
                ah[mt][2] = lds32(o00 + 16);
                ah[mt][3] = lds32(o10 + 16);
                al[mt][0] = lds32(o00 + TILEB);
                al[mt][1] = lds32(o10 + TILEB);
                al[mt][2] = lds32(o00 + 16 + TILEB);
                al[mt][3] = lds32(o10 + 16 + TILEB);
            }
            uint32_t bh[4][2], bl[4][2];
#pragma unroll
            for (int nt = 0; nt < 4; nt++) {
                int n0 = (wn << 5) + (nt << 3) + gid;
                uint32_t o = s0 + 2 * TILEB + n0 * ROWB + c0 * 2;
                bh[nt][0] = lds32(o);
                bh[nt][1] = lds32(o + 16);
                bl[nt][0] = lds32(o + TILEB);
                bl[nt][1] = lds32(o + 16 + TILEB);
            }
#pragma unroll
            for (int mt = 0; mt < 4; mt++)
#pragma unroll
                for (int nt = 0; nt < 4; nt++) {
                    mma16816(acc[mt][nt], ah[mt], bh[nt]);  // Ah*Wh
                    mma16816(acc[mt][nt], ah[mt], bl[nt]);  // Ah*Wl
                    mma16816(acc[mt][nt], al[mt], bh[nt]);  // Al*Wh
                }
        }
        __syncthreads();   // all reads done before next overwrite of this stage
    }

    // epilogue: bias + store (fp32)
#pragma unroll
    for (int mt = 0; mt < 4; mt++) {
        int r = bm + (wm << 6) + (mt << 4) + gid;
#pragma unroll
        for (int nt = 0; nt < 4; nt++) {
            int c = bn + (wn << 5) + (nt << 3) + (tig << 1);
            float b0 = bias[c], b1 = bias[c + 1];
            *reinterpret_cast<float2*>(&C[(size_t)r * Ntot + c]) =
                make_float2(acc[mt][nt][0] + b0, acc[mt][nt][1] + b1);
            *reinterpret_cast<float2*>(&C[(size_t)(r + 8) * Ntot + c]) =
                make_float2(acc[mt][nt][2] + b0, acc[mt][nt][3] + b1);
        }
    }
}

// ================= f32x2 SIMT GEMM (init + logits) =================
__device__ __forceinline__ unsigned long long fma2(unsigned long long a,
                                                   unsigned long long b,
                                                   unsigned long long c) {
    unsigned long long d;
    asm("fma.rn.f32x2 %0, %1, %2, %3;" : "=l"(d) : "l"(a), "l"(b), "l"(c));
    return d;
}
__device__ __forceinline__ unsigned long long pack2(float x) {
    unsigned long long d;
    asm("mov.b64 %0, {%1, %2};" : "=l"(d) : "f"(x), "f"(x));
    return d;
}

template <bool NGUARD, bool TANH>
__global__ void __launch_bounds__(256, 2)
gemm_kernel(const float* __restrict__ A, const float* __restrict__ W,
            const float* __restrict__ bias, float* __restrict__ C,
            int N, int K) {
    __shared__ float As[16][128];
    __shared__ float Ws[16][128];

    const int tid  = threadIdx.x;
    const int tcol = (tid & 15) << 3;
    const int trow = (tid >> 4) << 3;
    const int bm   = blockIdx.y * 128;
    const int bn   = blockIdx.x * 128;
    const int lrow = tid >> 2;
    const int lc4  = (tid & 3) << 2;

    unsigned long long acc[8][4];
#pragma unroll
    for (int i = 0; i < 8; i++)
#pragma unroll
        for (int j = 0; j < 4; j++) acc[i][j] = 0ULL;

    for (int k0 = 0; k0 < K; k0 += 16) {
#pragma unroll
        for (int l = 0; l < 2; l++) {
            int row = lrow + (l << 6);
            float4 av = *reinterpret_cast<const float4*>(
                &A[(size_t)(bm + row) * K + k0 + lc4]);
            As[lc4 + 0][row] = av.x;
            As[lc4 + 1][row] = av.y;
            As[lc4 + 2][row] = av.z;
            As[lc4 + 3][row] = av.w;
            float4 wv = make_float4(0.f, 0.f, 0.f, 0.f);
            if (!NGUARD || (bn + row) < N)
                wv = *reinterpret_cast<const float4*>(
                    &W[(size_t)(bn + row) * K + k0 + lc4]);
            Ws[lc4 + 0][row] = wv.x;
            Ws[lc4 + 1][row] = wv.y;
            Ws[lc4 + 2][row] = wv.z;
            Ws[lc4 + 3][row] = wv.w;
        }
        __syncthreads();
#pragma unroll
        for (int k = 0; k < 16; k++) {
            ulonglong2 b01 = *reinterpret_cast<const ulonglong2*>(&Ws[k][tcol]);
            ulonglong2 b23 = *reinterpret_cast<const ulonglong2*>(&Ws[k][tcol + 4]);
            float4 a0 = *reinterpret_cast<const float4*>(&As[k][trow]);
            float4 a1 = *reinterpret_cast<const float4*>(&As[k][trow + 4]);
            float av8[8] = {a0.x, a0.y, a0.z, a0.w, a1.x, a1.y, a1.z, a1.w};
#pragma unroll
            for (int i = 0; i < 8; i++) {
                unsigned long long ap = pack2(av8[i]);
                acc[i][0] = fma2(ap, b01.x, acc[i][0]);
                acc[i][1] = fma2(ap, b01.y, acc[i][1]);
                acc[i][2] = fma2(ap, b23.x, acc[i][2]);
                acc[i][3] = fma2(ap, b23.y, acc[i][3]);
            }
        }
        __syncthreads();
    }

#pragma unroll
    for (int i = 0; i < 8; i++) {
        int row = bm + trow + i;
#pragma unroll
        for (int j = 0; j < 4; j++) {
            int col = bn + tcol + 2 * j;
            if (NGUARD && col >= N) continue;
            float lo = __uint_as_float((unsigned)(acc[i][j] & 0xffffffffULL));
            float hi = __uint_as_float((unsigned)(acc[i][j] >> 32));
            float v0 = lo + bias[col];
            if (TANH) v0 = tanhf(v0);
            if (!NGUARD || (col + 1) < N) {
                float v1 = hi + bias[col + 1];
                if (TANH) v1 = tanhf(v1);
                *reinterpret_cast<float2*>(&C[(size_t)row * N + col]) =
                    make_float2(v0, v1);
            } else {
                C[(size_t)row * N + col] = v0;
            }
        }
    }
}

// ================= small kernels =================
__device__ __forceinline__ void split_write(float v, __nv_bfloat16* hi,
                                            __nv_bfloat16* lo, int i) {
    __nv_bfloat16 h = __float2bfloat16(v);
    hi[i] = h;
    lo[i] = __float2bfloat16(v - __bfloat162float(h));
}

__global__ void split_kernel(const float* __restrict__ src,
                             __nv_bfloat16* __restrict__ hi,
                             __nv_bfloat16* __restrict__ lo, int n) {
    int i = blockIdx.x * blockDim.x + threadIdx.x;
    if (i < n) split_write(src[i], hi, lo, i);
}

__global__ void splitpad_w1_kernel(const float* __restrict__ w) {
    int idx = blockIdx.x * blockDim.x + threadIdx.x;
    if (idx >= G3 * IN1P) return;
    int n = idx / IN1P, k = idx - n * IN1P;
    float v = (k < IN1) ? w[(size_t)n * IN1 + k] : 0.0f;
    split_write(v, g_w1h, g_w1l, idx);
}

__global__ void init_oidx_kernel() {
    int b = blockIdx.x * blockDim.x + threadIdx.x;
    if (b < BSZ) g_oidx[b] = ROLL - 1;
}

__global__ void build_inp_kernel(const float* __restrict__ rhy,
                                 const float* __restrict__ z1,
                                 const float* __restrict__ cond, int t) {
    int idx = blockIdx.x * blockDim.x + threadIdx.x;
    if (idx >= BSZ * IN1P) return;
    int b = idx / IN1P, c = idx - b * IN1P;
    float v;
    if (c < ROLL) {
        v = (c == g_oidx[b]) ? 1.0f : 0.0f;
    } else if (c < ROLL + RHY) {
        v = rhy[(size_t)b * TT * RHY + (size_t)t * RHY + (c - ROLL)];
    } else if (c < ROLL + RHY + NZ1) {
        v = z1[(size_t)b * NZ1 + (c - ROLL - RHY)];
    } else if (c < IN1) {
        v = cond[(size_t)b * TT * COND + (size_t)t * COND + (c - ROLL - RHY - NZ1)];
    } else {
        v = 0.0f;
    }
    split_write(v, g_xh, g_xl, idx);
}

__global__ void gru_update_kernel(const float* __restrict__ gi,
                                  const float* __restrict__ gh,
                                  const float* hprev, float* hout,
                                  __nv_bfloat16* __restrict__ houth,
                                  __nv_bfloat16* __restrict__ houtl) {
    int idx = blockIdx.x * blockDim.x + threadIdx.x;
    if (idx >= BSZ * HH) return;
    int b = idx >> 10, j = idx & (HH - 1);
    size_t o = (size_t)b * G3 + j;
    float ir = gi[o], iz = gi[o + HH], in_ = gi[o + 2 * HH];
    float hr = gh[o], hz = gh[o + HH], hn = gh[o + 2 * HH];
    float r = 1.0f / (1.0f + expf(-(ir + hr)));
    float z = 1.0f / (1.0f + expf(-(iz + hz)));
    float n = tanhf(in_ + r * hn);
    float h = (1.0f - z) * n + z * hprev[idx];
    hout[idx] = h;
    split_write(h, houth, houtl, idx);
}

__global__ void softmax_argmax_kernel(float* __restrict__ recon, int t) {
    int gw = (blockIdx.x * blockDim.x + threadIdx.x) >> 5;
    int lane = threadIdx.x & 31;
    if (gw >= BSZ) return;
    const float* lg = &g_logits[(size_t)gw * ROLL];
    float vals[5];
    float mx = -1e30f;
#pragma unroll
    for (int j = 0; j < 5; j++) {
        int n = lane + 32 * j;
        vals[j] = (n < ROLL) ? lg[n] : -1e30f;
        mx = fmaxf(mx, vals[j]);
    }
#pragma unroll
    for (int s = 16; s; s >>= 1) mx = fmaxf(mx, __shfl_xor_sync(0xffffffffu, mx, s));
    float se = 0.0f;
#pragma unroll
    for (int j = 0; j < 5; j++) {
        int n = lane + 32 * j;
        if (n < ROLL) se += expf(vals[j] - mx);
    }
#pragma unroll
    for (int s = 16; s; s >>= 1) se += __shfl_xor_sync(0xffffffffu, se, s);
    float lse = logf(se);
    float* out = &recon[(size_t)gw * (TT * ROLL) + (size_t)t * ROLL];
#pragma unroll
    for (int j = 0; j < 5; j++) {
        int n = lane + 32 * j;
        if (n < ROLL) out[n] = vals[j] - mx - lse;
    }
    float bv = -1e30f;
    int bi = ROLL;
#pragma unroll
    for (int j = 0; j < 5; j++) {
        int n = lane + 32 * j;
        if (n < ROLL && vals[j] > bv) { bv = vals[j]; bi = n; }
    }
#pragma unroll
    for (int s = 16; s; s >>= 1) {
        float ov = __shfl_xor_sync(0xffffffffu, bv, s);
        int oi = __shfl_xor_sync(0xffffffffu, bi, s);
        if (ov > bv || (ov == bv && oi < bi)) { bv = ov; bi = oi; }
    }
    if (lane == 0) g_oidx[gw] = bi;
}

// ================= launch =================
extern "C" void kernel_launch(void* const* d_in, const int* in_sizes, int n_in,
                              void* d_out, int out_size) {
    const float* z1    = (const float*)d_in[0];
    const float* d1m   = (const float*)d_in[1];
    const float* d1s   = (const float*)d_in[2];
    const float* d2m   = (const float*)d_in[3];
    const float* d2s   = (const float*)d_in[4];
    const float* rhy   = (const float*)d_in[5];
    const float* cond  = (const float*)d_in[7];
    const float* w_ih1 = (const float*)d_in[9];
    const float* w_hh1 = (const float*)d_in[10];
    const float* b_ih1 = (const float*)d_in[11];
    const float* b_hh1 = (const float*)d_in[12];
    const float* w_ih2 = (const float*)d_in[13];
    const float* w_hh2 = (const float*)d_in[14];
    const float* b_ih2 = (const float*)d_in[15];
    const float* b_hh2 = (const float*)d_in[16];
    const float* w_init = (const float*)d_in[17];
    const float* b_init = (const float*)d_in[18];
    const float* w_out  = (const float*)d_in[19];
    const float* b_out  = (const float*)d_in[20];

    float* out = (float*)d_out;
    float* recon = out;

    float *p_gi, *p_gh, *p_h1, *p_h2, *p_lg;
    __nv_bfloat16 *p_xh, *p_xl, *p_h1h, *p_h1l, *p_h2h, *p_h2l;
    __nv_bfloat16 *p_w1h, *p_w1l, *p_whh1h, *p_whh1l, *p_wih2h, *p_wih2l, *p_whh2h, *p_whh2l;
    cudaGetSymbolAddress((void**)&p_gi, g_gi);
    cudaGetSymbolAddress((void**)&p_gh, g_gh);
    cudaGetSymbolAddress((void**)&p_h1, g_h1);
    cudaGetSymbolAddress((void**)&p_h2, g_h2);
    cudaGetSymbolAddress((void**)&p_lg, g_logits);
    cudaGetSymbolAddress((void**)&p_xh, g_xh);
    cudaGetSymbolAddress((void**)&p_xl, g_xl);
    cudaGetSymbolAddress((void**)&p_h1h, g_h1h);
    cudaGetSymbolAddress((void**)&p_h1l, g_h1l);
    cudaGetSymbolAddress((void**)&p_h2h, g_h2h);
    cudaGetSymbolAddress((void**)&p_h2l, g_h2l);
    cudaGetSymbolAddress((void**)&p_w1h, g_w1h);
    cudaGetSymbolAddress((void**)&p_w1l, g_w1l);
    cudaGetSymbolAddress((void**)&p_whh1h, g_whh1h);
    cudaGetSymbolAddress((void**)&p_whh1l, g_whh1l);
    cudaGetSymbolAddress((void**)&p_wih2h, g_wih2h);
    cudaGetSymbolAddress((void**)&p_wih2l, g_wih2l);
    cudaGetSymbolAddress((void**)&p_whh2h, g_whh2h);
    cudaGetSymbolAddress((void**)&p_whh2l, g_whh2l);

    cudaFuncSetAttribute(gemm_mma, cudaFuncAttributeMaxDynamicSharedMemorySize, MMA_SMEM);

    // weight splits (every call: deterministic)
    splitpad_w1_kernel<<<(G3 * IN1P + 255) / 256, 256>>>(w_ih1);
    split_kernel<<<(G3 * HH + 255) / 256, 256>>>(w_hh1, p_whh1h, p_whh1l, G3 * HH);
    split_kernel<<<(G3 * HH + 255) / 256, 256>>>(w_ih2, p_wih2h, p_wih2l, G3 * HH);
    split_kernel<<<(G3 * HH + 255) / 256, 256>>>(w_hh2, p_whh2h, p_whh2l, G3 * HH);
    init_oidx_kernel<<<(BSZ + 255) / 256, 256>>>();

    // h1_0 = tanh(z1 @ w_init^T + b_init), then split
    gemm_kernel<false, true><<<dim3(HH / 128, BSZ / 128), 256>>>(
        z1, w_init, b_init, p_h1, HH, NZ1);
    split_kernel<<<(BSZ * HH + 255) / 256, 256>>>(p_h1, p_h1h, p_h1l, BSZ * HH);

    const dim3 mma_grid(G3 / 128, BSZ / 128);   // 24 x 32
    for (int t = 0; t < TT; t++) {
        build_inp_kernel<<<(BSZ * IN1P + 255) / 256, 256>>>(rhy, z1, cond, t);
        // GRU cell 1
        gemm_mma<<<mma_grid, 256, MMA_SMEM>>>(p_xh, p_xl, p_w1h, p_w1l, b_ih1, p_gi, G3, IN1P);
        gemm_mma<<<mma_grid, 256, MMA_SMEM>>>(p_h1h, p_h1l, p_whh1h, p_whh1l, b_hh1, p_gh, G3, HH);
        gru_update_kernel<<<(BSZ * HH + 255) / 256, 256>>>(p_gi, p_gh, p_h1, p_h1, p_h1h, p_h1l);
        // GRU cell 2 (h2 := h1 at t==0)
        gemm_mma<<<mma_grid, 256, MMA_SMEM>>>(p_h1h, p_h1l, p_wih2h, p_wih2l, b_ih2, p_gi, G3, HH);
        const __nv_bfloat16* h2ph = (t == 0) ? p_h1h : p_h2h;
        const __nv_bfloat16* h2pl = (t == 0) ? p_h1l : p_h2l;
        const float* h2pf = (t == 0) ? p_h1 : p_h2;
        gemm_mma<<<mma_grid, 256, MMA_SMEM>>>(h2ph, h2pl, p_whh2h, p_whh2l, b_hh2, p_gh, G3, HH);
        gru_update_kernel<<<(BSZ * HH + 255) / 256, 256>>>(p_gi, p_gh, h2pf, p_h2, p_h2h, p_h2l);
        // logits -> log_softmax -> recon + argmax feedback (fp32 SIMT)
        gemm_kernel<true, false><<<dim3(2, BSZ / 128), 256>>>(
            p_h2, w_out, b_out, p_lg, ROLL, HH);
        softmax_argmax_kernel<<<BSZ / 4, 128>>>(recon, t);
    }

    // pass-through outputs
    const size_t RECON_N = (size_t)BSZ * TT * ROLL;
    const size_t RHY_N   = (size_t)BSZ * TT * RHY;
    const size_t DIS_N   = (size_t)BSZ * NZ1;
    cudaMemcpyAsync(out + RECON_N, rhy, RHY_N * sizeof(float), cudaMemcpyDeviceToDevice);
    cudaMemcpyAsync(out + RECON_N + RHY_N, d1m, DIS_N * sizeof(float), cudaMemcpyDeviceToDevice);
    cudaMemcpyAsync(out + RECON_N + RHY_N + DIS_N, d1s, DIS_N * sizeof(float), cudaMemcpyDeviceToDevice);
    cudaMemcpyAsync(out + RECON_N + RHY_N + 2 * DIS_N, d2m, DIS_N * sizeof(float), cudaMemcpyDeviceToDevice);
    cudaMemcpyAsync(out + RECON_N + RHY_N + 3 * DIS_N, d2s, DIS_N * sizeof(float), cudaMemcpyDeviceToDevice);
}